// round 4
// baseline (speedup 1.0000x reference)
#include <cuda_runtime.h>
#include <cuda_bf16.h>
#include <cstdint>

#define NTOK 32768
#define NEXP 64
#define CDIM 1024
#define CAPV 2048

#define BM 128
#define BN 64
#define BK 16
#define ASTR 132
#define BSTR 68

__device__ float g_logits[(size_t)NTOK * NEXP];
__device__ int   g_top[2 * NTOK];

typedef unsigned long long u64;

__device__ __forceinline__ u64 pack2(float lo, float hi) {
    u64 r;
    asm("mov.b64 %0, {%1, %2};" : "=l"(r)
        : "r"(__float_as_uint(lo)), "r"(__float_as_uint(hi)));
    return r;
}
__device__ __forceinline__ void fma2(u64& d, u64 a, u64 b) {
    asm("fma.rn.f32x2 %0, %1, %2, %0;" : "+l"(d) : "l"(a), "l"(b));
}
__device__ __forceinline__ void unpack2(u64 v, float& lo, float& hi) {
    uint32_t l, h;
    asm("mov.b64 {%0, %1}, %2;" : "=r"(l), "=r"(h) : "l"(v));
    lo = __uint_as_float(l);
    hi = __uint_as_float(h);
}

// ---------------------------------------------------------------------------
// Kernel 1: logits = x @ w^T  (M=32768, N=64, K=1024), fp32, FFMA2 inner loop
// ---------------------------------------------------------------------------
__global__ __launch_bounds__(128) void gemm_kernel(
    const float* __restrict__ x, const float* __restrict__ w)
{
    __shared__ float As[BK * ASTR];
    __shared__ float Bs[BK * BSTR];

    const int tid  = threadIdx.x;
    const int row0 = blockIdx.x * BM;
    const int ty   = tid >> 3;   // 0..15
    const int tx   = tid & 7;    // 0..7

    u64 acc[8][4];
#pragma unroll
    for (int i = 0; i < 8; i++)
#pragma unroll
        for (int j = 0; j < 4; j++) acc[i][j] = 0ull;

    for (int k0 = 0; k0 < CDIM; k0 += BK) {
        // Load A tile 128x16 (transposed into As[k][m])
#pragma unroll
        for (int j = 0; j < 4; j++) {
            int l = tid + j * 128;          // 0..511
            int m = l >> 2, q = l & 3;
            const float4 v = *reinterpret_cast<const float4*>(
                x + (size_t)(row0 + m) * CDIM + k0 + q * 4);
            As[(q * 4 + 0) * ASTR + m] = v.x;
            As[(q * 4 + 1) * ASTR + m] = v.y;
            As[(q * 4 + 2) * ASTR + m] = v.z;
            As[(q * 4 + 3) * ASTR + m] = v.w;
        }
        // Load B tile 64x16 (transposed into Bs[k][e])
#pragma unroll
        for (int j = 0; j < 2; j++) {
            int l = tid + j * 128;          // 0..255
            int e = l >> 2, q = l & 3;
            const float4 v = *reinterpret_cast<const float4*>(
                w + (size_t)e * CDIM + k0 + q * 4);
            Bs[(q * 4 + 0) * BSTR + e] = v.x;
            Bs[(q * 4 + 1) * BSTR + e] = v.y;
            Bs[(q * 4 + 2) * BSTR + e] = v.z;
            Bs[(q * 4 + 3) * BSTR + e] = v.w;
        }
        __syncthreads();

#pragma unroll
        for (int k = 0; k < BK; k++) {
            float4 a0 = *reinterpret_cast<float4*>(&As[k * ASTR + ty * 8]);
            float4 a1 = *reinterpret_cast<float4*>(&As[k * ASTR + ty * 8 + 4]);
            float4 b0 = *reinterpret_cast<float4*>(&Bs[k * BSTR + tx * 8]);
            float4 b1 = *reinterpret_cast<float4*>(&Bs[k * BSTR + tx * 8 + 4]);
            u64 av[8];
            av[0] = pack2(a0.x, a0.x); av[1] = pack2(a0.y, a0.y);
            av[2] = pack2(a0.z, a0.z); av[3] = pack2(a0.w, a0.w);
            av[4] = pack2(a1.x, a1.x); av[5] = pack2(a1.y, a1.y);
            av[6] = pack2(a1.z, a1.z); av[7] = pack2(a1.w, a1.w);
            u64 bv[4];
            bv[0] = pack2(b0.x, b0.y); bv[1] = pack2(b0.z, b0.w);
            bv[2] = pack2(b1.x, b1.y); bv[3] = pack2(b1.z, b1.w);
#pragma unroll
            for (int i = 0; i < 8; i++)
#pragma unroll
                for (int j = 0; j < 4; j++) fma2(acc[i][j], av[i], bv[j]);
        }
        __syncthreads();
    }

    // Store logits
#pragma unroll
    for (int i = 0; i < 8; i++) {
        float o[8];
#pragma unroll
        for (int j = 0; j < 4; j++) unpack2(acc[i][j], o[2 * j], o[2 * j + 1]);
        float* dst = g_logits + (size_t)(row0 + ty * 8 + i) * NEXP + tx * 8;
        *reinterpret_cast<float4*>(dst)     = make_float4(o[0], o[1], o[2], o[3]);
        *reinterpret_cast<float4*>(dst + 4) = make_float4(o[4], o[5], o[6], o[7]);
    }
}

// ---------------------------------------------------------------------------
// Kernel 2: top-2 + softmax. One warp per token.
// ---------------------------------------------------------------------------
__global__ __launch_bounds__(1024) void top2_kernel(
    float* __restrict__ out_probs, float* __restrict__ out_idx)
{
    const int t    = blockIdx.x * (blockDim.x >> 5) + (threadIdx.x >> 5);
    const int lane = threadIdx.x & 31;

    float v0 = g_logits[(size_t)t * NEXP + lane];
    float v1 = g_logits[(size_t)t * NEXP + 32 + lane];

    float a1, a2; int j1, j2;
    if (v0 >= v1) { a1 = v0; j1 = lane;      a2 = v1; j2 = lane + 32; }
    else          { a1 = v1; j1 = lane + 32; a2 = v0; j2 = lane;      }

#pragma unroll
    for (int o = 16; o > 0; o >>= 1) {
        float b1 = __shfl_down_sync(0xffffffffu, a1, o);
        int   k1 = __shfl_down_sync(0xffffffffu, j1, o);
        float b2 = __shfl_down_sync(0xffffffffu, a2, o);
        int   k2 = __shfl_down_sync(0xffffffffu, j2, o);
        bool first = (a1 > b1) || (a1 == b1 && j1 < k1);
        if (first) {
            bool s = (a2 > b1) || (a2 == b1 && j2 < k1);
            if (!s) { a2 = b1; j2 = k1; }
        } else {
            bool s = (b2 > a1) || (b2 == a1 && k2 < j1);
            if (s) { a1 = b1; j1 = k1; a2 = b2; j2 = k2; }
            else   { a2 = a1; j2 = j1; a1 = b1; j1 = k1; }
        }
    }

    if (lane == 0) {
        float d  = a2 - a1;               // <= 0
        float ed = __expf(d);
        float p1 = 1.0f / (1.0f + ed);
        float p2 = ed / (1.0f + ed);
        g_top[t]        = j1;
        g_top[NTOK + t] = j2;
        out_probs[2 * t]     = p1;
        out_probs[2 * t + 1] = p2;
        out_idx[2 * t]       = (float)j1;
        out_idx[2 * t + 1]   = (float)j2;
    }
}

// ---------------------------------------------------------------------------
// Kernel 3: per-expert sequential rank (k-major cumsum), capacity drop, scatter.
// One CTA per expert; scans top1 stream then top2 stream with carried scan.
// ---------------------------------------------------------------------------
__global__ __launch_bounds__(1024) void rank_kernel(
    float* __restrict__ out_mask, float* __restrict__ out_probs,
    float* __restrict__ out_rank)
{
    const int e    = blockIdx.x;
    const int tid  = threadIdx.x;
    const int lane = tid & 31;
    const int wid  = tid >> 5;

    __shared__ int wsum[32];
    __shared__ int stotal;

    int carry = 0;
#pragma unroll 1
    for (int s = 0; s < 2; s++) {
        const int4* p = reinterpret_cast<const int4*>(g_top + s * NTOK);
#pragma unroll 1
        for (int c = 0; c < NTOK / 4096; c++) {
            int4 v = p[c * 1024 + tid];
            int m0 = (v.x == e), m1 = (v.y == e), m2 = (v.z == e), m3 = (v.w == e);
            int cs = m0 + m1 + m2 + m3;

            int inc = cs;
#pragma unroll
            for (int o = 1; o < 32; o <<= 1) {
                int t2 = __shfl_up_sync(0xffffffffu, inc, o);
                if (lane >= o) inc += t2;
            }
            if (lane == 31) wsum[wid] = inc;
            __syncthreads();
            if (wid == 0) {
                int wv = wsum[lane];
                int winc = wv;
#pragma unroll
                for (int o = 1; o < 32; o <<= 1) {
                    int t2 = __shfl_up_sync(0xffffffffu, winc, o);
                    if (lane >= o) winc += t2;
                }
                wsum[lane] = winc - wv;            // exclusive warp prefix
                if (lane == 31) stotal = winc;     // chunk total
            }
            __syncthreads();

            int r  = carry + wsum[wid] + (inc - cs);   // exclusive rank base
            int i0 = (c * 1024 + tid) * 4;

            if (m0) {
                int oi = (i0 + 0) * 2 + s;
                out_rank[oi] = (float)r;
                if (r < CAPV) out_mask[(size_t)oi * NEXP + e] = 1.0f;
                else out_probs[oi] = 0.0f;
                r++;
            }
            if (m1) {
                int oi = (i0 + 1) * 2 + s;
                out_rank[oi] = (float)r;
                if (r < CAPV) out_mask[(size_t)oi * NEXP + e] = 1.0f;
                else out_probs[oi] = 0.0f;
                r++;
            }
            if (m2) {
                int oi = (i0 + 2) * 2 + s;
                out_rank[oi] = (float)r;
                if (r < CAPV) out_mask[(size_t)oi * NEXP + e] = 1.0f;
                else out_probs[oi] = 0.0f;
                r++;
            }
            if (m3) {
                int oi = (i0 + 3) * 2 + s;
                out_rank[oi] = (float)r;
                if (r < CAPV) out_mask[(size_t)oi * NEXP + e] = 1.0f;
                else out_probs[oi] = 0.0f;
                r++;
            }
            carry += stotal;
            __syncthreads();   // protect wsum/stotal before next chunk
        }
    }
}

// ---------------------------------------------------------------------------
extern "C" void kernel_launch(void* const* d_in, const int* in_sizes, int n_in,
                              void* d_out, int out_size)
{
    const float* x = (const float*)d_in[0];
    const float* w = (const float*)d_in[1];

    float* out       = (float*)d_out;
    float* out_mask  = out;                                   // N*2*64
    float* out_probs = out + (size_t)NTOK * 2 * NEXP;         // N*2
    float* out_idx   = out_probs + NTOK * 2;                  // N*2
    float* out_rank  = out_idx + NTOK * 2;                    // N*2

    cudaMemsetAsync(out_mask, 0, (size_t)NTOK * 2 * NEXP * sizeof(float));
    gemm_kernel<<<NTOK / BM, 128>>>(x, w);
    top2_kernel<<<NTOK / 32, 1024>>>(out_probs, out_idx);
    rank_kernel<<<NEXP, 1024>>>(out_mask, out_probs, out_rank);
}